// round 9
// baseline (speedup 1.0000x reference)
#include <cuda_runtime.h>
#include <cuda.h>
#include <cuda_bf16.h>
#include <cstdint>

#define N_TOTAL 8388608   // 2^23

__device__ float2 g_scratch[N_TOTAL];   // transposed intermediate

__host__ __device__ __forceinline__ constexpr int brev_c(int x, int K) {
    int r = 0;
    for (int b = 0; b < K; b++) r |= ((x >> b) & 1) << (K - 1 - b);
    return r;
}

__device__ __forceinline__ float2 cmul(float2 a, float2 w) {
    return make_float2(a.x * w.x - a.y * w.y, a.x * w.y + a.y * w.x);
}

// In-register DIF butterfly network, K stages at global stage offset S0,
// twiddles prefetched up front (indices data-independent).
template <int S0, int K>
__device__ __forceinline__ void bnet_pf(float2* a, unsigned jj,
                                        const float2* __restrict__ W) {
    float2 tw[(1 << K) - 1];
#pragma unroll
    for (int u = 0; u < K; u++) {
#pragma unroll
        for (int c = 0; c < (1 << u); c++) {
            unsigned idx = (jj << (22 - S0 - u)) + ((unsigned)c << (22 - u));
            tw[(1 << u) - 1 + c] = __ldg(&W[idx]);
        }
    }
#pragma unroll
    for (int u = 0; u < K; u++) {
        const int half = 1 << (K - 1 - u);
#pragma unroll
        for (int t = 0; t < (1 << K) / 2; t++) {
            const int q1 = ((t & ~(half - 1)) << 1) | (t & (half - 1));
            const int q2 = q1 + half;
            const int c = brev_c(q1, K) & ((1 << u) - 1);
            float2 w = tw[(1 << u) - 1 + c];
            float2 p = cmul(a[q2], w);
            float2 tt = a[q1];
            a[q1] = make_float2(tt.x + p.x, tt.y + p.y);
            a[q2] = make_float2(tt.x - p.x, tt.y - p.y);
        }
    }
}

#define SMEM_ELEMS 16384
#define SMEM_BYTES (SMEM_ELEMS * 8)

__device__ __forceinline__ uint32_t smem_u32(const void* p) {
    uint32_t a;
    asm("{ .reg .u64 t; cvta.to.shared.u64 t, %1; cvt.u32.u64 %0, t; }"
        : "=r"(a) : "l"(p));
    return a;
}

// ============================================================================
// Kernel A: stages [0,11). R6-verbatim. Tile = 8 bases x 2048 q, rounds 4+4+3.
// Output transposed: Yt[brev11(q)*4096 + base].
// ============================================================================
__device__ __forceinline__ unsigned phA(unsigned q, unsigned g) {
    unsigned l = (q << 3) | g;
    return l ^ (((l >> 6) & 1u) << 3);
}

__global__ void __launch_bounds__(512, 1)
fft_kA(const float* __restrict__ Xr, const float2* __restrict__ W,
       float2* __restrict__ Yt) {
    extern __shared__ float2 sm2[];

    const unsigned t = threadIdx.x;
    const unsigned g = t & 7u;
    const unsigned rest = t >> 3;
    const unsigned base = blockIdx.x * 8u + g;

#pragma unroll
    for (int pass = 0; pass < 2; pass++) {
        unsigned low7 = rest + 64u * pass;
        float2 a[16];
#pragma unroll
        for (int x = 0; x < 16; x++)
            a[x] = make_float2(
                __ldg(&Xr[base + ((((unsigned)x << 7) | low7) << 12)]), 0.0f);
        bnet_pf<0, 4>(a, 0u, W);
#pragma unroll
        for (int x = 0; x < 16; x++)
            sm2[phA(((unsigned)x << 7) | low7, g)] = a[x];
    }
    __syncthreads();

#pragma unroll
    for (int pass = 0; pass < 2; pass++) {
        unsigned idx2 = rest + 64u * pass;
        unsigned lo3 = idx2 & 7u;
        unsigned H = idx2 >> 3;
        unsigned jj = __brev(H) >> 28;
        float2 a[16];
#pragma unroll
        for (int x = 0; x < 16; x++)
            a[x] = sm2[phA((H << 7) | ((unsigned)x << 3) | lo3, g)];
        bnet_pf<4, 4>(a, jj, W);
#pragma unroll
        for (int x = 0; x < 16; x++)
            sm2[phA((H << 7) | ((unsigned)x << 3) | lo3, g)] = a[x];
    }
    __syncthreads();

#pragma unroll
    for (int pass = 0; pass < 4; pass++) {
        unsigned B = rest + 64u * pass;
        unsigned jj = __brev(B) >> 24;
        float2 a[8];
#pragma unroll
        for (int x = 0; x < 8; x++)
            a[x] = sm2[phA((B << 3) | (unsigned)x, g)];
        bnet_pf<8, 3>(a, jj, W);
#pragma unroll
        for (int x = 0; x < 8; x++) {
            unsigned C = ((unsigned)brev_c(x, 3) << 8) | jj;
            Yt[C * 4096u + base] = a[x];
        }
    }
}

// ============================================================================
// Kernel B: stages [11,23). Tile = 4 j x 4096 q, rounds 4+4+4.
// Round 3 computes IN-PLACE into TMA box layout [C*4+jg]; output written by
// 16 TMA 2D bulk stores (box [8 floats, 256 C]) -> zero STG wavefronts.
// Swizzle phB2 verified conflict-free for R1/R2 STS+LDS and R3 LDS; linear
// staging STS 2-phase via the l3-major B assignment.
// ============================================================================
__device__ __forceinline__ unsigned phB2(unsigned q, unsigned jg) {
    unsigned l = (q << 2) | jg;
    l ^= (l >> 4) & 3u;
    l ^= ((l >> 11) & 7u) << 2;
    return l;
}

__device__ __forceinline__ void tma_store2d(const CUtensorMap* m, int cx,
                                            int cy, uint32_t saddr) {
    asm volatile(
        "cp.async.bulk.tensor.2d.global.shared::cta.tile.bulk_group "
        "[%0, {%1, %2}], [%3];"
        :: "l"(m), "r"(cx), "r"(cy), "r"(saddr) : "memory");
}

__global__ void __launch_bounds__(512, 1)
fft_kB(const float2* __restrict__ In, const float2* __restrict__ W,
       const __grid_constant__ CUtensorMap tmap) {
    extern __shared__ float2 sm2[];

    const unsigned t = threadIdx.x;
    const unsigned j0 = blockIdx.x * 4u;

    // round 1: bits q[11:8], S0=11. jg1 = t>>7 (warp-uniform jB), coalesced.
    {
        const unsigned jg1 = t >> 7;
        const unsigned lowt = t & 127u;
        const unsigned jB1 = j0 + jg1;
#pragma unroll
        for (int pass = 0; pass < 2; pass++) {
            unsigned low8 = lowt + 128u * pass;
            float2 a[16];
#pragma unroll
            for (int x = 0; x < 16; x++)
                a[x] = __ldg(&In[jB1 * 4096u + (((unsigned)x << 8) | low8)]);
            bnet_pf<11, 4>(a, jB1, W);
#pragma unroll
            for (int x = 0; x < 16; x++)
                sm2[phB2(((unsigned)x << 8) | low8, jg1)] = a[x];
        }
    }
    __syncthreads();

    const unsigned jg = t & 3u;
    const unsigned jB = j0 + jg;

    // round 2: bits q[7:4], S0=15, jj = jB + brev4(q[11:8])<<11
    {
        const unsigned rest = t >> 2;
#pragma unroll
        for (int pass = 0; pass < 2; pass++) {
            unsigned idx2 = rest + 128u * pass;
            unsigned lo4 = idx2 & 15u;
            unsigned H = idx2 >> 4;
            unsigned jj = jB + ((__brev(H) >> 28) << 11);
            float2 a[16];
#pragma unroll
            for (int x = 0; x < 16; x++)
                a[x] = sm2[phB2((H << 8) | ((unsigned)x << 4) | lo4, jg)];
            bnet_pf<15, 4>(a, jj, W);
#pragma unroll
            for (int x = 0; x < 16; x++)
                sm2[phB2((H << 8) | ((unsigned)x << 4) | lo4, jg)] = a[x];
        }
    }
    __syncthreads();

    // round 3: bits q[3:0], S0=19. B = l3<<5 | w<<1 | p assignment.
    // Read everything (2 B's worth), barrier, overwrite tile in box layout.
    {
        const unsigned l3 = (t >> 2) & 7u;
        const unsigned w = t >> 5;
        const unsigned B0 = (l3 << 5) | (w << 1);
        const unsigned B1 = B0 | 1u;

        float2 a0[16], a1[16];
#pragma unroll
        for (int x = 0; x < 16; x++)
            a0[x] = sm2[phB2((B0 << 4) | (unsigned)x, jg)];
#pragma unroll
        for (int x = 0; x < 16; x++)
            a1[x] = sm2[phB2((B1 << 4) | (unsigned)x, jg)];

        unsigned Brev0 = __brev(B0) >> 24;
        unsigned Brev1 = __brev(B1) >> 24;
        bnet_pf<19, 4>(a0, jB + (Brev0 << 11), W);
        bnet_pf<19, 4>(a1, jB + (Brev1 << 11), W);

        __syncthreads();   // all tile reads done -> safe to overwrite

#pragma unroll
        for (int x = 0; x < 16; x++) {
            unsigned C0 = ((unsigned)brev_c(x, 4) << 8) | Brev0;
            unsigned C1 = ((unsigned)brev_c(x, 4) << 8) | Brev1;
            sm2[(C0 << 2) | jg] = a0[x];
            sm2[(C1 << 2) | jg] = a1[x];
        }
    }
    __syncthreads();

    // 16 TMA chunk stores: chunk k covers C in [256k, 256k+256)
    if (t < 16) {
        asm volatile("fence.proxy.async.shared::cta;" ::: "memory");
        uint32_t sa = smem_u32(sm2) + t * 8192u;   // 256 C * 4 j * 8B
        tma_store2d(&tmap, (int)(blockIdx.x * 8u), (int)(t * 256u), sa);
        asm volatile("cp.async.bulk.commit_group;" ::: "memory");
        asm volatile("cp.async.bulk.wait_group 0;" ::: "memory");
    }
}

// ---------------------------------------------------------------------------
typedef CUresult (*EncodeFn)(
    CUtensorMap*, CUtensorMapDataType, cuuint32_t, void*,
    const cuuint64_t*, const cuuint64_t*, const cuuint32_t*, const cuuint32_t*,
    CUtensorMapInterleave, CUtensorMapSwizzle, CUtensorMapL2promotion,
    CUtensorMapFloatOOBfill);

extern "C" void kernel_launch(void* const* d_in, const int* in_sizes, int n_in,
                              void* d_out, int out_size) {
    const float* inp = (const float*)d_in[0];
    const float2* w = (const float2*)d_in[1];

    float2* scr = nullptr;
    cudaGetSymbolAddress((void**)&scr, g_scratch);

    static EncodeFn enc = nullptr;
    if (!enc) {
        void* p = nullptr;
        cudaDriverEntryPointQueryResult qr;
        cudaGetDriverEntryPoint("cuTensorMapEncodeTiled", &p,
                                cudaEnableDefault, &qr);
        enc = (EncodeFn)p;
    }

    // d_out viewed as float tensor: dims [4096 (j*2), 4096 (C)], row = 16KB
    CUtensorMap tmap;
    cuuint64_t gdim[2] = {4096, 4096};
    cuuint64_t gstr[1] = {4096ull * 4ull};
    cuuint32_t box[2] = {8, 256};
    cuuint32_t estr[2] = {1, 1};
    enc(&tmap, CU_TENSOR_MAP_DATA_TYPE_FLOAT32, 2, d_out,
        gdim, gstr, box, estr,
        CU_TENSOR_MAP_INTERLEAVE_NONE, CU_TENSOR_MAP_SWIZZLE_NONE,
        CU_TENSOR_MAP_L2_PROMOTION_L2_128B,
        CU_TENSOR_MAP_FLOAT_OOB_FILL_NONE);

    cudaFuncSetAttribute(fft_kA, cudaFuncAttributeMaxDynamicSharedMemorySize,
                         SMEM_BYTES);
    cudaFuncSetAttribute(fft_kB, cudaFuncAttributeMaxDynamicSharedMemorySize,
                         SMEM_BYTES);

    fft_kA<<<512, 512, SMEM_BYTES>>>(inp, w, scr);       // stages 0..10
    fft_kB<<<512, 512, SMEM_BYTES>>>(scr, w, tmap);      // stages 11..22
}

// round 10
// speedup vs baseline: 1.0853x; 1.0853x over previous
#include <cuda_runtime.h>
#include <cuda_bf16.h>
#include <cstdint>

#define N_TOTAL 8388608   // 2^23

__device__ float2 g_scratch[N_TOTAL];   // transposed intermediate (L2-resident handoff)

__host__ __device__ __forceinline__ constexpr int brev_c(int x, int K) {
    int r = 0;
    for (int b = 0; b < K; b++) r |= ((x >> b) & 1) << (K - 1 - b);
    return r;
}

__device__ __forceinline__ float2 cmul(float2 a, float2 w) {
    return make_float2(a.x * w.x - a.y * w.y, a.x * w.y + a.y * w.x);
}

// In-register DIF butterfly network, K stages at global stage offset S0,
// all twiddles prefetched up front (indices data-independent).
template <int S0, int K>
__device__ __forceinline__ void bnet_pf(float2* a, unsigned jj,
                                        const float2* __restrict__ W) {
    float2 tw[(1 << K) - 1];
#pragma unroll
    for (int u = 0; u < K; u++) {
#pragma unroll
        for (int c = 0; c < (1 << u); c++) {
            unsigned idx = (jj << (22 - S0 - u)) + ((unsigned)c << (22 - u));
            tw[(1 << u) - 1 + c] = __ldg(&W[idx]);
        }
    }
#pragma unroll
    for (int u = 0; u < K; u++) {
        const int half = 1 << (K - 1 - u);
#pragma unroll
        for (int t = 0; t < (1 << K) / 2; t++) {
            const int q1 = ((t & ~(half - 1)) << 1) | (t & (half - 1));
            const int q2 = q1 + half;
            const int c = brev_c(q1, K) & ((1 << u) - 1);
            float2 w = tw[(1 << u) - 1 + c];
            float2 p = cmul(a[q2], w);
            float2 tt = a[q1];
            a[q1] = make_float2(tt.x + p.x, tt.y + p.y);
            a[q2] = make_float2(tt.x - p.x, tt.y - p.y);
        }
    }
}

#define SMEM_ELEMS 16384
#define SMEM_BYTES (SMEM_ELEMS * 8)

// ============================================================================
// Kernel A: stages [0,11). Tile = 8 bases (g) x 2048 q. Rounds 4+4+3.
// float2 smem, XOR swizzle. Input read with .cs (single use, evict-first);
// scratch written with default policy (keep resident in L2 for kB).
// Output transposed: Yt[brev11(q)*4096 + base].
// ============================================================================
__device__ __forceinline__ unsigned phA(unsigned q, unsigned g) {
    unsigned l = (q << 3) | g;
    return l ^ (((l >> 6) & 1u) << 3);
}

__global__ void __launch_bounds__(512, 1)
fft_kA(const float* __restrict__ Xr, const float2* __restrict__ W,
       float2* __restrict__ Yt) {
    extern __shared__ float2 sm2[];

    const unsigned t = threadIdx.x;
    const unsigned g = t & 7u;
    const unsigned rest = t >> 3;              // 0..63
    const unsigned base = blockIdx.x * 8u + g;

    // round 1: bits q[10:7], S0=0, jj=0 (gmem load, imag=0)
#pragma unroll
    for (int pass = 0; pass < 2; pass++) {
        unsigned low7 = rest + 64u * pass;     // q[6:0]
        float2 a[16];
#pragma unroll
        for (int x = 0; x < 16; x++)
            a[x] = make_float2(
                __ldcs(&Xr[base + ((((unsigned)x << 7) | low7) << 12)]), 0.0f);
        bnet_pf<0, 4>(a, 0u, W);
#pragma unroll
        for (int x = 0; x < 16; x++)
            sm2[phA(((unsigned)x << 7) | low7, g)] = a[x];
    }
    __syncthreads();

    // round 2: bits q[6:3], S0=4, jj = brev4(q[10:7])
#pragma unroll
    for (int pass = 0; pass < 2; pass++) {
        unsigned idx2 = rest + 64u * pass;     // 0..127
        unsigned lo3 = idx2 & 7u;              // q[2:0]
        unsigned H = idx2 >> 3;                // q[10:7]
        unsigned jj = __brev(H) >> 28;
        float2 a[16];
#pragma unroll
        for (int x = 0; x < 16; x++)
            a[x] = sm2[phA((H << 7) | ((unsigned)x << 3) | lo3, g)];
        bnet_pf<4, 4>(a, jj, W);
#pragma unroll
        for (int x = 0; x < 16; x++)
            sm2[phA((H << 7) | ((unsigned)x << 3) | lo3, g)] = a[x];
    }
    __syncthreads();

    // round 3: bits q[2:0], S0=8, K=3, jj = brev8(q[10:3]); write transposed
#pragma unroll
    for (int pass = 0; pass < 4; pass++) {
        unsigned B = rest + 64u * pass;        // q[10:3], 0..255
        unsigned jj = __brev(B) >> 24;
        float2 a[8];
#pragma unroll
        for (int x = 0; x < 8; x++)
            a[x] = sm2[phA((B << 3) | (unsigned)x, g)];
        bnet_pf<8, 3>(a, jj, W);
#pragma unroll
        for (int x = 0; x < 8; x++) {
            unsigned C = ((unsigned)brev_c(x, 3) << 8) | jj;  // brev11(q)
            Yt[C * 4096u + base] = a[x];       // default .wb: stay in L2
        }
    }
}

// ============================================================================
// Kernel B: stages [11,23). Tile = 4 j x 4096 q. Rounds 4+4+4.
// Scratch read with .cs (LAST use: hit L2 then evict-first, freeing space for
// W + output). Output written with .cs (streaming). Round 1 lane map: 32
// consecutive q per warp, single jB. Output: Out[(brev12(q) << 11) + j].
// ============================================================================
__device__ __forceinline__ unsigned phB(unsigned q, unsigned js) {
    unsigned l = (q << 2) | js;
    return l ^ ((l >> 4) & 3u) ^ (((l >> 6) & 3u) << 2);
}

__global__ void __launch_bounds__(512, 1)
fft_kB(const float2* __restrict__ In, const float2* __restrict__ W,
       float2* __restrict__ Out) {
    extern __shared__ float2 sm2[];

    const unsigned t = threadIdx.x;
    const unsigned j0 = blockIdx.x * 4u;

    // round 1: bits q[11:8], S0=11. jg1 = t>>7 (warp-uniform jB),
    // 32 consecutive q per warp => coalesced LDG + uniform twiddles.
    {
        const unsigned jg1 = t >> 7;           // 0..3
        const unsigned lowt = t & 127u;
        const unsigned jB1 = j0 + jg1;
#pragma unroll
        for (int pass = 0; pass < 2; pass++) {
            unsigned low8 = lowt + 128u * pass;  // q[7:0]
            float2 a[16];
#pragma unroll
            for (int x = 0; x < 16; x++)
                a[x] = __ldcs(&In[jB1 * 4096u + (((unsigned)x << 8) | low8)]);
            bnet_pf<11, 4>(a, jB1, W);
#pragma unroll
            for (int x = 0; x < 16; x++) {
                unsigned q = ((unsigned)x << 8) | low8;
                sm2[phB(q, jg1)] = a[x];
            }
        }
    }
    __syncthreads();

    const unsigned jg = t & 3u;
    const unsigned rest = t >> 2;              // 0..127
    const unsigned jB = j0 + jg;

    // round 2: bits q[7:4], S0=15, jj = jB + brev4(q[11:8])<<11
#pragma unroll
    for (int pass = 0; pass < 2; pass++) {
        unsigned idx2 = rest + 128u * pass;    // 0..255
        unsigned lo4 = idx2 & 15u;             // q[3:0]
        unsigned H = idx2 >> 4;                // q[11:8]
        unsigned jj = jB + ((__brev(H) >> 28) << 11);
        float2 a[16];
#pragma unroll
        for (int x = 0; x < 16; x++)
            a[x] = sm2[phB((H << 8) | ((unsigned)x << 4) | lo4, jg)];
        bnet_pf<15, 4>(a, jj, W);
#pragma unroll
        for (int x = 0; x < 16; x++)
            sm2[phB((H << 8) | ((unsigned)x << 4) | lo4, jg)] = a[x];
    }
    __syncthreads();

    // round 3: bits q[3:0], S0=19, jj = jB + brev8(q[11:4])<<11; write out
#pragma unroll
    for (int pass = 0; pass < 2; pass++) {
        unsigned B = rest + 128u * pass;       // q[11:4], 0..255
        unsigned Brev = __brev(B) >> 24;
        unsigned jj = jB + (Brev << 11);
        float2 a[16];
#pragma unroll
        for (int x = 0; x < 16; x++)
            a[x] = sm2[phB((B << 4) | (unsigned)x, jg)];
        bnet_pf<19, 4>(a, jj, W);
#pragma unroll
        for (int x = 0; x < 16; x++) {
            unsigned C = ((unsigned)brev_c(x, 4) << 8) | Brev;  // brev12(q)
            __stcs(&Out[(C << 11) + jB], a[x]);
        }
    }
}

// ---------------------------------------------------------------------------
extern "C" void kernel_launch(void* const* d_in, const int* in_sizes, int n_in,
                              void* d_out, int out_size) {
    const float* inp = (const float*)d_in[0];
    const float2* w = (const float2*)d_in[1];
    float2* out = (float2*)d_out;

    float2* scr = nullptr;
    cudaGetSymbolAddress((void**)&scr, g_scratch);

    cudaFuncSetAttribute(fft_kA, cudaFuncAttributeMaxDynamicSharedMemorySize,
                         SMEM_BYTES);
    cudaFuncSetAttribute(fft_kB, cudaFuncAttributeMaxDynamicSharedMemorySize,
                         SMEM_BYTES);

    fft_kA<<<512, 512, SMEM_BYTES>>>(inp, w, scr);   // stages 0..10
    fft_kB<<<512, 512, SMEM_BYTES>>>(scr, w, out);   // stages 11..22
}